// round 2
// baseline (speedup 1.0000x reference)
#include <cuda_runtime.h>
#include <math.h>

// ---------------------------------------------------------------------------
// SMModel: multiscale spatially-varying conv network.
// Direct fused implementation:
//   per (b, o, tile): loop i over input channels; compute h (20ch, halo-1)
//   into smem from image tile; grouped conv2 (9 outputs) per pixel with 2x2
//   register micro-tiling; apply per-pixel 3x3 kernel to x patches; elu.
// ---------------------------------------------------------------------------

#define NC    8
#define HID   20
#define TX    32
#define TY    8

// scratch: img1(8*64*64) img2(8*32*32) x0a/x0b(8*8*128*128) x1a/x1b(8*8*64*64) x2a/x2b(8*8*32*32)
__device__ float g_buf[2793472];

__device__ __forceinline__ float elu_f(float v) {
    return v > 0.f ? v : (expf(v) - 1.f);
}

// ---------------------------------------------------------------------------
// sm_block: out[b,o,:,:] = elu( sum_i sum_k Kf[b,(o,i),k,:,:] * xp[b,i,k,:,:] )
//   h  = conv3x3(image, W1_g) + b1_g          (zero-pad, per group 20 ch)
//   Kf = conv3x3_group(h, W2_g) + b2_g        (h zero OUTSIDE domain)
// ---------------------------------------------------------------------------
__global__ __launch_bounds__(64, 6) void smblock_kernel(
    const float* __restrict__ img,   // (B, N, N)
    const float* __restrict__ xin,   // (B, nc_in, N, N)
    const float* __restrict__ W1,    // (P*HID, 9)
    const float* __restrict__ b1,    // (P*HID)
    const float* __restrict__ W2,    // (P*9, HID, 9)
    const float* __restrict__ b2,    // (P*9)
    float* __restrict__ out,         // (B, NC, N, N)
    int N, int nc_in)
{
    __shared__ float simg[(TY + 4) * (TX + 4)];          // 12*36
    __shared__ float sh[HID * (TY + 2) * (TX + 2)];      // 20*10*34
    __shared__ float sxs[(TY + 2) * (TX + 2)];           // 10*34
    __shared__ float sW1[HID * 9];
    __shared__ float sb1[HID];
    __shared__ float sW2[9 * HID * 9];
    __shared__ float sb2[9];

    const int tilesX = N / TX;
    const int tx0 = (blockIdx.x % tilesX) * TX;
    const int ty0 = (blockIdx.x / tilesX) * TY;
    const int o = blockIdx.y;
    const int b = blockIdx.z;
    const int tid = threadIdx.x;

    // image tile with halo 2, zero-padded outside domain
    const float* imgb = img + (size_t)b * N * N;
    for (int idx = tid; idx < (TY + 4) * (TX + 4); idx += 64) {
        int ly = idx / (TX + 4), lx = idx % (TX + 4);
        int gy = ty0 - 2 + ly, gx = tx0 - 2 + lx;
        simg[idx] = (gy >= 0 && gy < N && gx >= 0 && gx < N) ? imgb[gy * N + gx] : 0.f;
    }

    const int pqx = (tid & 15) * 2;   // pixel x within tile (2x2 micro-tile)
    const int pqy = (tid >> 4) * 2;   // pixel y within tile

    float outacc[2][2] = {{0.f, 0.f}, {0.f, 0.f}};

    for (int i = 0; i < nc_in; i++) {
        const int g = o * nc_in + i;
        __syncthreads();  // previous iteration done with smem

        // group weights -> smem
        const float* w1g = W1 + (size_t)g * HID * 9;
        for (int idx = tid; idx < HID * 9; idx += 64) sW1[idx] = w1g[idx];
        if (tid < HID) sb1[tid] = b1[g * HID + tid];
        const float* w2g = W2 + (size_t)g * 9 * HID * 9;
        for (int idx = tid; idx < 9 * HID * 9; idx += 64) sW2[idx] = w2g[idx];
        if (tid < 9) sb2[tid] = b2[g * 9 + tid];

        // x channel i tile with halo 1, zero-padded outside domain
        const float* xb = xin + ((size_t)b * nc_in + i) * N * N;
        for (int idx = tid; idx < (TY + 2) * (TX + 2); idx += 64) {
            int ly = idx / (TX + 2), lx = idx % (TX + 2);
            int gy = ty0 - 1 + ly, gx = tx0 - 1 + lx;
            sxs[idx] = (gy >= 0 && gy < N && gx >= 0 && gx < N) ? xb[gy * N + gx] : 0.f;
        }
        __syncthreads();

        // h on (HID, TY+2, TX+2), masked to zero outside domain, 2-wide in x
        for (int idx = tid; idx < HID * (TY + 2) * ((TX + 2) / 2); idx += 64) {
            int c = idx / ((TY + 2) * 17);
            int rem = idx % ((TY + 2) * 17);
            int hy = rem / 17, hx = (rem % 17) * 2;
            int gy = ty0 - 1 + hy;
            float v0 = sb1[c], v1 = sb1[c];
#pragma unroll
            for (int ry = 0; ry < 3; ry++) {
#pragma unroll
                for (int rx = 0; rx < 3; rx++) {
                    float w = sW1[c * 9 + ry * 3 + rx];
                    v0 += w * simg[(hy + ry) * (TX + 4) + hx + rx];
                    v1 += w * simg[(hy + ry) * (TX + 4) + hx + rx + 1];
                }
            }
            int gx0 = tx0 - 1 + hx;
            bool iny = (gy >= 0 && gy < N);
            sh[(c * (TY + 2) + hy) * (TX + 2) + hx]     = (iny && gx0 >= 0 && gx0 < N) ? v0 : 0.f;
            sh[(c * (TY + 2) + hy) * (TX + 2) + hx + 1] = (iny && gx0 + 1 >= 0 && gx0 + 1 < N) ? v1 : 0.f;
        }
        __syncthreads();

        // grouped conv2 -> per-pixel 3x3 kernel values acc[k], 2x2 micro-tile
        float acc[9][2][2];
#pragma unroll
        for (int k = 0; k < 9; k++) {
            float bb = sb2[k];
            acc[k][0][0] = bb; acc[k][0][1] = bb; acc[k][1][0] = bb; acc[k][1][1] = bb;
        }
#pragma unroll 1
        for (int c = 0; c < HID; c++) {
            float hreg[4][4];
#pragma unroll
            for (int ry = 0; ry < 4; ry++)
#pragma unroll
                for (int rx = 0; rx < 4; rx++)
                    hreg[ry][rx] = sh[(c * (TY + 2) + pqy + ry) * (TX + 2) + pqx + rx];
#pragma unroll
            for (int k = 0; k < 9; k++) {
#pragma unroll
                for (int r = 0; r < 9; r++) {
                    const int ry = r / 3, rx = r % 3;
                    float w = sW2[(k * HID + c) * 9 + r];
                    acc[k][0][0] += w * hreg[ry][rx];
                    acc[k][0][1] += w * hreg[ry][rx + 1];
                    acc[k][1][0] += w * hreg[ry + 1][rx];
                    acc[k][1][1] += w * hreg[ry + 1][rx + 1];
                }
            }
        }

        // apply per-pixel kernel to x patches (xp zero-padded)
        float xreg[4][4];
#pragma unroll
        for (int ry = 0; ry < 4; ry++)
#pragma unroll
            for (int rx = 0; rx < 4; rx++)
                xreg[ry][rx] = sxs[(pqy + ry) * (TX + 2) + pqx + rx];
#pragma unroll
        for (int k = 0; k < 9; k++) {
            const int ay = k / 3, ax = k % 3;
            outacc[0][0] += acc[k][0][0] * xreg[0 + ay][0 + ax];
            outacc[0][1] += acc[k][0][1] * xreg[0 + ay][1 + ax];
            outacc[1][0] += acc[k][1][0] * xreg[1 + ay][0 + ax];
            outacc[1][1] += acc[k][1][1] * xreg[1 + ay][1 + ax];
        }
    }

    float* ob = out + ((size_t)b * NC + o) * N * N;
#pragma unroll
    for (int sy = 0; sy < 2; sy++)
#pragma unroll
        for (int sx = 0; sx < 2; sx++)
            ob[(ty0 + pqy + sy) * N + (tx0 + pqx + sx)] = elu_f(outacc[sy][sx]);
}

// ---------------------------------------------------------------------------
// 2x2 mean downsample: in (C, 2No, 2No) -> out (C, No, No)
// ---------------------------------------------------------------------------
__global__ void down_kernel(const float* __restrict__ in, float* __restrict__ out,
                            int C, int No)
{
    int idx = blockIdx.x * blockDim.x + threadIdx.x;
    int total = C * No * No;
    if (idx >= total) return;
    int c = idx / (No * No);
    int p = idx % (No * No);
    int h = p / No, w = p % No;
    int Ni = No * 2;
    const float* ib = in + (size_t)c * Ni * Ni;
    float s = ib[(2 * h) * Ni + 2 * w] + ib[(2 * h) * Ni + 2 * w + 1]
            + ib[(2 * h + 1) * Ni + 2 * w] + ib[(2 * h + 1) * Ni + 2 * w + 1];
    out[idx] = 0.25f * s;
}

// ---------------------------------------------------------------------------
// combine: v = x + up(x1) + up(up(x2)); y = elu(w5 v + b5); out = w6 y + b6
// ---------------------------------------------------------------------------
__global__ void combine_kernel(const float* __restrict__ x0,
                               const float* __restrict__ x1,
                               const float* __restrict__ x2,
                               const float* __restrict__ w5, const float* __restrict__ b5,
                               const float* __restrict__ w6, const float* __restrict__ b6,
                               float* __restrict__ out)
{
    int idx = blockIdx.x * blockDim.x + threadIdx.x;
    if (idx >= 8 * 128 * 128) return;
    int b = idx / (128 * 128);
    int p = idx % (128 * 128);
    int h = p / 128, w = p % 128;
    float v[NC];
#pragma unroll
    for (int c = 0; c < NC; c++) {
        v[c] = x0[((size_t)b * NC + c) * 16384 + p]
             + x1[((size_t)b * NC + c) * 4096 + (h >> 1) * 64 + (w >> 1)]
             + x2[((size_t)b * NC + c) * 1024 + (h >> 2) * 32 + (w >> 2)];
    }
    float accv = b6[0];
#pragma unroll
    for (int o = 0; o < NC; o++) {
        float y = b5[o];
#pragma unroll
        for (int c = 0; c < NC; c++) y += w5[o * NC + c] * v[c];
        y = elu_f(y);
        accv += w6[o] * y;
    }
    out[idx] = accv;
}

// ---------------------------------------------------------------------------
extern "C" void kernel_launch(void* const* d_in, const int* in_sizes, int n_in,
                              void* d_out, int out_size)
{
    const float* image = (const float*)d_in[0];   // (8,128,128)
    const float* x_in  = (const float*)d_in[1];   // (8,1,128,128)
    const float* iW1   = (const float*)d_in[2];   // (160,1,3,3)
    const float* ib1   = (const float*)d_in[3];   // (160)
    const float* iW2   = (const float*)d_in[4];   // (72,20,3,3)
    const float* ib2   = (const float*)d_in[5];   // (72)
    const float* bW1   = (const float*)d_in[6];   // (12,1280,1,3,3)
    const float* bb1   = (const float*)d_in[7];   // (12,1280)
    const float* bW2   = (const float*)d_in[8];   // (12,576,20,3,3)
    const float* bb2   = (const float*)d_in[9];   // (12,576)
    const float* w5    = (const float*)d_in[10];
    const float* b5    = (const float*)d_in[11];
    const float* w6    = (const float*)d_in[12];
    const float* b6    = (const float*)d_in[13];

    float* base;
    cudaGetSymbolAddress((void**)&base, g_buf);
    float* img1 = base;                         // 8*64*64   = 32768
    float* img2 = img1 + 32768;                 // 8*32*32   = 8192
    float* x0a  = img2 + 8192;                  // 1048576
    float* x0b  = x0a + 1048576;
    float* x1a  = x0b + 1048576;                // 262144
    float* x1b  = x1a + 262144;
    float* x2a  = x1b + 262144;                 // 65536
    float* x2b  = x2a + 65536;

    // image pyramid
    down_kernel<<<(8 * 64 * 64 + 255) / 256, 256>>>(image, img1, 8, 64);
    down_kernel<<<(8 * 32 * 32 + 255) / 256, 256>>>(img1, img2, 8, 32);

    dim3 gridF((128 / TX) * (128 / TY), NC, 8);   // 64 tiles
    dim3 grid1((64 / TX) * (64 / TY), NC, 8);     // 16 tiles
    dim3 grid2((32 / TX) * (32 / TY), NC, 8);     // 4 tiles

    // init block: nc_in = 1
    smblock_kernel<<<gridF, 64>>>(image, x_in, iW1, ib1, iW2, ib2, x0a, 128, 1);

    // downsample x
    down_kernel<<<(64 * 64 * 64 + 255) / 256, 256>>>(x0a, x1a, 64, 64);
    down_kernel<<<(64 * 32 * 32 + 255) / 256, 256>>>(x1a, x2a, 64, 32);

    float *xc = x0a, *xn = x0b;
    float *x1c = x1a, *x1n = x1b;
    float *x2c = x2a, *x2n = x2b;

    for (int t = 0; t < 4; t++) {
        int k0 = 3 * t, k1 = 3 * t + 1, k2 = 3 * t + 2;
        smblock_kernel<<<gridF, 64>>>(image, xc,
            bW1 + (size_t)k0 * 1280 * 9, bb1 + (size_t)k0 * 1280,
            bW2 + (size_t)k0 * 576 * 180, bb2 + (size_t)k0 * 576,
            xn, 128, NC);
        { float* t_ = xc; xc = xn; xn = t_; }

        smblock_kernel<<<grid1, 64>>>(img1, x1c,
            bW1 + (size_t)k1 * 1280 * 9, bb1 + (size_t)k1 * 1280,
            bW2 + (size_t)k1 * 576 * 180, bb2 + (size_t)k1 * 576,
            x1n, 64, NC);
        { float* t_ = x1c; x1c = x1n; x1n = t_; }

        smblock_kernel<<<grid2, 64>>>(img2, x2c,
            bW1 + (size_t)k2 * 1280 * 9, bb1 + (size_t)k2 * 1280,
            bW2 + (size_t)k2 * 576 * 180, bb2 + (size_t)k2 * 576,
            x2n, 32, NC);
        { float* t_ = x2c; x2c = x2n; x2n = t_; }
    }

    combine_kernel<<<(8 * 128 * 128 + 255) / 256, 256>>>(
        xc, x1c, x2c, w5, b5, w6, b6, (float*)d_out);
}

// round 3
// speedup vs baseline: 1.4801x; 1.4801x over previous
#include <cuda_runtime.h>
#include <math.h>

// ---------------------------------------------------------------------------
// SMModel — composed-convolution implementation.
// conv2(group) ∘ conv1 collapses into a per-(group,k) 5x5 kernel on the image
// (weights are batch-independent). Border pixels get inclusion-exclusion
// corrections for the reference's zero-padding of h outside the domain.
// ---------------------------------------------------------------------------

#define NC    8
#define HID   20
#define TX    32
#define TY    8

// scratch layout (floats):
//   img1 8*64*64 | img2 8*32*32 | x0a/x0b 8*8*128^2 | x1a/x1b 8*8*64^2 |
//   x2a/x2b 8*8*32^2 | tabW5 9*64*9*25 | tabB 9*64*9
__device__ float g_buf[2928256];

__device__ __forceinline__ float elu_f(float v) {
    return v > 0.f ? v : (expf(v) - 1.f);
}

// ---------------------------------------------------------------------------
// compose: build class tables
//   cls 0: all q (interior)      cls 1: qy=-1 (top)    cls 2: qy=+1 (bottom)
//   cls 3: qx=-1 (left)          cls 4: qx=+1 (right)
//   cls 5..8: single-q corners (-1,-1) (-1,+1) (+1,-1) (+1,+1)
// T[cls][g][k][5x5], Bias[cls][g][k]
// ---------------------------------------------------------------------------
__global__ void compose_kernel(const float* __restrict__ W1, const float* __restrict__ b1,
                               const float* __restrict__ W2, const float* __restrict__ b2,
                               float* __restrict__ tabW5, float* __restrict__ tabB, int P)
{
    int idx = blockIdx.x * blockDim.x + threadIdx.x;
    if (idx >= P * 9 * 9) return;
    int cls = idx / (P * 9);
    int rem = idx % (P * 9);
    int g = rem / 9, k = rem % 9;

    float T[25];
#pragma unroll
    for (int j = 0; j < 25; j++) T[j] = 0.f;
    float bias = (cls == 0) ? b2[g * 9 + k] : 0.f;

    for (int q = 0; q < 9; q++) {
        int qy = q / 3 - 1, qx = q % 3 - 1;
        bool in;
        switch (cls) {
            case 0: in = true; break;
            case 1: in = (qy == -1); break;
            case 2: in = (qy == 1); break;
            case 3: in = (qx == -1); break;
            case 4: in = (qx == 1); break;
            case 5: in = (qy == -1 && qx == -1); break;
            case 6: in = (qy == -1 && qx == 1); break;
            case 7: in = (qy == 1 && qx == -1); break;
            default: in = (qy == 1 && qx == 1); break;
        }
        if (!in) continue;
        for (int c = 0; c < HID; c++) {
            float w2 = W2[((size_t)(g * 9 + k) * HID + c) * 9 + q];
            bias += b1[g * HID + c] * w2;
            float* Trow = T + (qy + 2) * 5 + (qx + 2);  // offset for r=( -1,-1 ) is +(-1+1)*5...
#pragma unroll
            for (int r = 0; r < 9; r++) {
                int ry = r / 3 - 1, rx = r % 3 - 1;
                T[(qy + ry + 2) * 5 + (qx + rx + 2)] += w2 * W1[(size_t)(g * HID + c) * 9 + r];
            }
            (void)Trow;
        }
    }

    float* To = tabW5 + ((size_t)(cls * P + g) * 9 + k) * 25;
#pragma unroll
    for (int j = 0; j < 25; j++) To[j] = T[j];
    tabB[(size_t)(cls * P + g) * 9 + k] = bias;
}

// ---------------------------------------------------------------------------
// border correction for one micro-pixel (SY,SX): acc[k] += sgn * cls-table term
// ---------------------------------------------------------------------------
template <int SY, int SX>
__device__ __forceinline__ void corr_cls(float (&acc)[9][2][2],
                                         const float* __restrict__ tabW5,
                                         const float* __restrict__ tabB,
                                         int cls, int P, int g, float sgn,
                                         const float* __restrict__ simg,
                                         int pqy, int pqx)
{
    const float* t = tabW5 + ((size_t)(cls * P + g) * 9) * 25;
    const float* bt = tabB + (size_t)(cls * P + g) * 9;
#pragma unroll
    for (int k = 0; k < 9; k++) {
        float s = bt[k];
        for (int dy = 0; dy < 5; dy++)
            for (int dx = 0; dx < 5; dx++)
                s += t[k * 25 + dy * 5 + dx] *
                     simg[(pqy + SY + dy) * (TX + 4) + pqx + SX + dx];
        acc[k][SY][SX] += sgn * s;
    }
}

// ---------------------------------------------------------------------------
// sm_block via composed 5x5 kernel
// ---------------------------------------------------------------------------
__global__ __launch_bounds__(64) void smblock5_kernel(
    const float* __restrict__ img,     // (B, N, N)
    const float* __restrict__ xin,     // (B, nc_in, N, N)
    const float* __restrict__ tabW5,   // (9, P, 9, 25)
    const float* __restrict__ tabB,    // (9, P, 9)
    float* __restrict__ out,           // (B, NC, N, N)
    int N, int nc_in, int P)
{
    __shared__ float simg[(TY + 4) * (TX + 4)];
    __shared__ float sxs[(TY + 2) * (TX + 2)];
    __shared__ float sW5[9 * 25];
    __shared__ float sB[9];

    const int tilesX = N / TX;
    const int tx0 = (blockIdx.x % tilesX) * TX;
    const int ty0 = (blockIdx.x / tilesX) * TY;
    const int o = blockIdx.y;
    const int b = blockIdx.z;
    const int tid = threadIdx.x;

    // image tile, halo 2, zero-padded
    const float* imgb = img + (size_t)b * N * N;
    for (int idx = tid; idx < (TY + 4) * (TX + 4); idx += 64) {
        int ly = idx / (TX + 4), lx = idx % (TX + 4);
        int gy = ty0 - 2 + ly, gx = tx0 - 2 + lx;
        simg[idx] = (gy >= 0 && gy < N && gx >= 0 && gx < N) ? imgb[gy * N + gx] : 0.f;
    }
    __syncthreads();

    const int pqx = (tid & 15) * 2;
    const int pqy = (tid >> 4) * 2;

    // per-thread image window 6x6 (fixed across i)
    float ir[6][6];
#pragma unroll
    for (int dy = 0; dy < 6; dy++)
#pragma unroll
        for (int dx = 0; dx < 6; dx++)
            ir[dy][dx] = simg[(pqy + dy) * (TX + 4) + pqx + dx];

    const bool borderTile = (ty0 == 0) || (ty0 + TY == N) || (tx0 == 0) || (tx0 + TX == N);

    float outacc[2][2] = {{0.f, 0.f}, {0.f, 0.f}};

    for (int i = 0; i < nc_in; i++) {
        const int g = o * nc_in + i;
        __syncthreads();

        // interior table -> smem
        const float* t0 = tabW5 + ((size_t)g * 9) * 25;
        for (int idx = tid; idx < 225; idx += 64) sW5[idx] = t0[idx];
        if (tid < 9) sB[tid] = tabB[(size_t)g * 9 + tid];

        // x channel tile, halo 1, zero-padded
        const float* xb = xin + ((size_t)b * nc_in + i) * N * N;
        for (int idx = tid; idx < (TY + 2) * (TX + 2); idx += 64) {
            int ly = idx / (TX + 2), lx = idx % (TX + 2);
            int gy = ty0 - 1 + ly, gx = tx0 - 1 + lx;
            sxs[idx] = (gy >= 0 && gy < N && gx >= 0 && gx < N) ? xb[gy * N + gx] : 0.f;
        }
        __syncthreads();

        // Kf via 5x5, 2x2 micro-tile
        float acc[9][2][2];
#pragma unroll
        for (int k = 0; k < 9; k++) {
            float bb = sB[k];
            acc[k][0][0] = bb; acc[k][0][1] = bb; acc[k][1][0] = bb; acc[k][1][1] = bb;
        }
#pragma unroll
        for (int dy = 0; dy < 5; dy++) {
#pragma unroll
            for (int dx = 0; dx < 5; dx++) {
                const int d = dy * 5 + dx;
                float i00 = ir[dy][dx],     i01 = ir[dy][dx + 1];
                float i10 = ir[dy + 1][dx], i11 = ir[dy + 1][dx + 1];
#pragma unroll
                for (int k = 0; k < 9; k++) {
                    float w = sW5[k * 25 + d];
                    acc[k][0][0] += w * i00;
                    acc[k][0][1] += w * i01;
                    acc[k][1][0] += w * i10;
                    acc[k][1][1] += w * i11;
                }
            }
        }

        // border corrections (inclusion-exclusion over invalid q sets)
        if (borderTile) {
#pragma unroll
            for (int sy = 0; sy < 2; sy++) {
#pragma unroll
                for (int sx = 0; sx < 2; sx++) {
                    int py = ty0 + pqy + sy, px = tx0 + pqx + sx;
                    bool Tt = (py == 0), Bb = (py == N - 1);
                    bool Ll = (px == 0), Rr = (px == N - 1);
                    if (sy == 0 && sx == 0) {
                        if (Tt) corr_cls<0,0>(acc, tabW5, tabB, 1, P, g, -1.f, simg, pqy, pqx);
                        if (Bb) corr_cls<0,0>(acc, tabW5, tabB, 2, P, g, -1.f, simg, pqy, pqx);
                        if (Ll) corr_cls<0,0>(acc, tabW5, tabB, 3, P, g, -1.f, simg, pqy, pqx);
                        if (Rr) corr_cls<0,0>(acc, tabW5, tabB, 4, P, g, -1.f, simg, pqy, pqx);
                        if (Tt && Ll) corr_cls<0,0>(acc, tabW5, tabB, 5, P, g, 1.f, simg, pqy, pqx);
                        if (Tt && Rr) corr_cls<0,0>(acc, tabW5, tabB, 6, P, g, 1.f, simg, pqy, pqx);
                        if (Bb && Ll) corr_cls<0,0>(acc, tabW5, tabB, 7, P, g, 1.f, simg, pqy, pqx);
                        if (Bb && Rr) corr_cls<0,0>(acc, tabW5, tabB, 8, P, g, 1.f, simg, pqy, pqx);
                    } else if (sy == 0 && sx == 1) {
                        if (Tt) corr_cls<0,1>(acc, tabW5, tabB, 1, P, g, -1.f, simg, pqy, pqx);
                        if (Bb) corr_cls<0,1>(acc, tabW5, tabB, 2, P, g, -1.f, simg, pqy, pqx);
                        if (Ll) corr_cls<0,1>(acc, tabW5, tabB, 3, P, g, -1.f, simg, pqy, pqx);
                        if (Rr) corr_cls<0,1>(acc, tabW5, tabB, 4, P, g, -1.f, simg, pqy, pqx);
                        if (Tt && Ll) corr_cls<0,1>(acc, tabW5, tabB, 5, P, g, 1.f, simg, pqy, pqx);
                        if (Tt && Rr) corr_cls<0,1>(acc, tabW5, tabB, 6, P, g, 1.f, simg, pqy, pqx);
                        if (Bb && Ll) corr_cls<0,1>(acc, tabW5, tabB, 7, P, g, 1.f, simg, pqy, pqx);
                        if (Bb && Rr) corr_cls<0,1>(acc, tabW5, tabB, 8, P, g, 1.f, simg, pqy, pqx);
                    } else if (sy == 1 && sx == 0) {
                        if (Tt) corr_cls<1,0>(acc, tabW5, tabB, 1, P, g, -1.f, simg, pqy, pqx);
                        if (Bb) corr_cls<1,0>(acc, tabW5, tabB, 2, P, g, -1.f, simg, pqy, pqx);
                        if (Ll) corr_cls<1,0>(acc, tabW5, tabB, 3, P, g, -1.f, simg, pqy, pqx);
                        if (Rr) corr_cls<1,0>(acc, tabW5, tabB, 4, P, g, -1.f, simg, pqy, pqx);
                        if (Tt && Ll) corr_cls<1,0>(acc, tabW5, tabB, 5, P, g, 1.f, simg, pqy, pqx);
                        if (Tt && Rr) corr_cls<1,0>(acc, tabW5, tabB, 6, P, g, 1.f, simg, pqy, pqx);
                        if (Bb && Ll) corr_cls<1,0>(acc, tabW5, tabB, 7, P, g, 1.f, simg, pqy, pqx);
                        if (Bb && Rr) corr_cls<1,0>(acc, tabW5, tabB, 8, P, g, 1.f, simg, pqy, pqx);
                    } else {
                        if (Tt) corr_cls<1,1>(acc, tabW5, tabB, 1, P, g, -1.f, simg, pqy, pqx);
                        if (Bb) corr_cls<1,1>(acc, tabW5, tabB, 2, P, g, -1.f, simg, pqy, pqx);
                        if (Ll) corr_cls<1,1>(acc, tabW5, tabB, 3, P, g, -1.f, simg, pqy, pqx);
                        if (Rr) corr_cls<1,1>(acc, tabW5, tabB, 4, P, g, -1.f, simg, pqy, pqx);
                        if (Tt && Ll) corr_cls<1,1>(acc, tabW5, tabB, 5, P, g, 1.f, simg, pqy, pqx);
                        if (Tt && Rr) corr_cls<1,1>(acc, tabW5, tabB, 6, P, g, 1.f, simg, pqy, pqx);
                        if (Bb && Ll) corr_cls<1,1>(acc, tabW5, tabB, 7, P, g, 1.f, simg, pqy, pqx);
                        if (Bb && Rr) corr_cls<1,1>(acc, tabW5, tabB, 8, P, g, 1.f, simg, pqy, pqx);
                    }
                }
            }
        }

        // apply per-pixel 3x3 kernel to x patches
        float xreg[4][4];
#pragma unroll
        for (int ry = 0; ry < 4; ry++)
#pragma unroll
            for (int rx = 0; rx < 4; rx++)
                xreg[ry][rx] = sxs[(pqy + ry) * (TX + 2) + pqx + rx];
#pragma unroll
        for (int k = 0; k < 9; k++) {
            const int ay = k / 3, ax = k % 3;
            outacc[0][0] += acc[k][0][0] * xreg[0 + ay][0 + ax];
            outacc[0][1] += acc[k][0][1] * xreg[0 + ay][1 + ax];
            outacc[1][0] += acc[k][1][0] * xreg[1 + ay][0 + ax];
            outacc[1][1] += acc[k][1][1] * xreg[1 + ay][1 + ax];
        }
    }

    float* ob = out + ((size_t)b * NC + o) * N * N;
#pragma unroll
    for (int sy = 0; sy < 2; sy++)
#pragma unroll
        for (int sx = 0; sx < 2; sx++)
            ob[(ty0 + pqy + sy) * N + (tx0 + pqx + sx)] = elu_f(outacc[sy][sx]);
}

// ---------------------------------------------------------------------------
__global__ void down_kernel(const float* __restrict__ in, float* __restrict__ out,
                            int C, int No)
{
    int idx = blockIdx.x * blockDim.x + threadIdx.x;
    int total = C * No * No;
    if (idx >= total) return;
    int c = idx / (No * No);
    int p = idx % (No * No);
    int h = p / No, w = p % No;
    int Ni = No * 2;
    const float* ib = in + (size_t)c * Ni * Ni;
    float s = ib[(2 * h) * Ni + 2 * w] + ib[(2 * h) * Ni + 2 * w + 1]
            + ib[(2 * h + 1) * Ni + 2 * w] + ib[(2 * h + 1) * Ni + 2 * w + 1];
    out[idx] = 0.25f * s;
}

__global__ void combine_kernel(const float* __restrict__ x0,
                               const float* __restrict__ x1,
                               const float* __restrict__ x2,
                               const float* __restrict__ w5, const float* __restrict__ b5,
                               const float* __restrict__ w6, const float* __restrict__ b6,
                               float* __restrict__ out)
{
    int idx = blockIdx.x * blockDim.x + threadIdx.x;
    if (idx >= 8 * 128 * 128) return;
    int b = idx / (128 * 128);
    int p = idx % (128 * 128);
    int h = p / 128, w = p % 128;
    float v[NC];
#pragma unroll
    for (int c = 0; c < NC; c++) {
        v[c] = x0[((size_t)b * NC + c) * 16384 + p]
             + x1[((size_t)b * NC + c) * 4096 + (h >> 1) * 64 + (w >> 1)]
             + x2[((size_t)b * NC + c) * 1024 + (h >> 2) * 32 + (w >> 2)];
    }
    float accv = b6[0];
#pragma unroll
    for (int o = 0; o < NC; o++) {
        float y = b5[o];
#pragma unroll
        for (int c = 0; c < NC; c++) y += w5[o * NC + c] * v[c];
        y = elu_f(y);
        accv += w6[o] * y;
    }
    out[idx] = accv;
}

// ---------------------------------------------------------------------------
extern "C" void kernel_launch(void* const* d_in, const int* in_sizes, int n_in,
                              void* d_out, int out_size)
{
    const float* image = (const float*)d_in[0];
    const float* x_in  = (const float*)d_in[1];
    const float* iW1   = (const float*)d_in[2];
    const float* ib1   = (const float*)d_in[3];
    const float* iW2   = (const float*)d_in[4];
    const float* ib2   = (const float*)d_in[5];
    const float* bW1   = (const float*)d_in[6];
    const float* bb1   = (const float*)d_in[7];
    const float* bW2   = (const float*)d_in[8];
    const float* bb2   = (const float*)d_in[9];
    const float* w5    = (const float*)d_in[10];
    const float* b5    = (const float*)d_in[11];
    const float* w6    = (const float*)d_in[12];
    const float* b6    = (const float*)d_in[13];

    float* base;
    cudaGetSymbolAddress((void**)&base, g_buf);
    float* img1 = base;                  // 32768
    float* img2 = img1 + 32768;          // 8192
    float* x0a  = img2 + 8192;           // 1048576
    float* x0b  = x0a + 1048576;
    float* x1a  = x0b + 1048576;         // 262144
    float* x1b  = x1a + 262144;
    float* x2a  = x1b + 262144;          // 65536
    float* x2b  = x2a + 65536;
    float* tabW5 = x2b + 65536;          // 9*64*9*25 = 129600
    float* tabB  = tabW5 + 129600;       // 9*64*9 = 5184

    // image pyramid
    down_kernel<<<(8 * 64 * 64 + 255) / 256, 256>>>(image, img1, 8, 64);
    down_kernel<<<(8 * 32 * 32 + 255) / 256, 256>>>(img1, img2, 8, 32);

    dim3 gridF((128 / TX) * (128 / TY), NC, 8);
    dim3 grid1((64 / TX) * (64 / TY), NC, 8);
    dim3 grid2((32 / TX) * (32 / TY), NC, 8);

    // init block (P = 8, nc_in = 1)
    compose_kernel<<<(8 * 81 + 127) / 128, 128>>>(iW1, ib1, iW2, ib2, tabW5, tabB, 8);
    smblock5_kernel<<<gridF, 64>>>(image, x_in, tabW5, tabB, x0a, 128, 1, 8);

    down_kernel<<<(64 * 64 * 64 + 255) / 256, 256>>>(x0a, x1a, 64, 64);
    down_kernel<<<(64 * 32 * 32 + 255) / 256, 256>>>(x1a, x2a, 64, 32);

    float *xc = x0a, *xn = x0b;
    float *x1c = x1a, *x1n = x1b;
    float *x2c = x2a, *x2n = x2b;

    for (int t = 0; t < 4; t++) {
        int k0 = 3 * t, k1 = 3 * t + 1, k2 = 3 * t + 2;

        compose_kernel<<<(64 * 81 + 127) / 128, 128>>>(
            bW1 + (size_t)k0 * 1280 * 9, bb1 + (size_t)k0 * 1280,
            bW2 + (size_t)k0 * 576 * 180, bb2 + (size_t)k0 * 576, tabW5, tabB, 64);
        smblock5_kernel<<<gridF, 64>>>(image, xc, tabW5, tabB, xn, 128, NC, 64);
        { float* t_ = xc; xc = xn; xn = t_; }

        compose_kernel<<<(64 * 81 + 127) / 128, 128>>>(
            bW1 + (size_t)k1 * 1280 * 9, bb1 + (size_t)k1 * 1280,
            bW2 + (size_t)k1 * 576 * 180, bb2 + (size_t)k1 * 576, tabW5, tabB, 64);
        smblock5_kernel<<<grid1, 64>>>(img1, x1c, tabW5, tabB, x1n, 64, NC, 64);
        { float* t_ = x1c; x1c = x1n; x1n = t_; }

        compose_kernel<<<(64 * 81 + 127) / 128, 128>>>(
            bW1 + (size_t)k2 * 1280 * 9, bb1 + (size_t)k2 * 1280,
            bW2 + (size_t)k2 * 576 * 180, bb2 + (size_t)k2 * 576, tabW5, tabB, 64);
        smblock5_kernel<<<grid2, 64>>>(img2, x2c, tabW5, tabB, x2n, 32, NC, 64);
        { float* t_ = x2c; x2c = x2n; x2n = t_; }
    }

    combine_kernel<<<(8 * 128 * 128 + 255) / 256, 256>>>(
        xc, x1c, x2c, w5, b5, w6, b6, (float*)d_out);
}

// round 4
// speedup vs baseline: 6.3159x; 4.2672x over previous
#include <cuda_runtime.h>
#include <math.h>

// ---------------------------------------------------------------------------
// SMModel — composed-5x5 + packed f32x2 implementation.
//  * compose: per (scale, cls, g, k) effective 5x5 tables (cls = interior /
//    4 edges / 4 corners, summing only valid q taps); cls0 also emitted as
//    duplicated (w,w) u64 pairs for the packed main kernel.
//  * main: interior formula everywhere, 3 scales fused in one launch,
//    128 thr/block, 2x4 pixels/thread, fma.rn.f32x2 inner loop.
//  * border: recompute the 4(N-1) edge pixels exactly from class tables.
// ---------------------------------------------------------------------------

#define NC    8
#define HID   20

typedef unsigned long long ull;

__device__ float g_buf[3287680];

__device__ __forceinline__ float elu_f(float v) {
    return v > 0.f ? v : (expf(v) - 1.f);
}

__device__ __forceinline__ ull pk(float lo, float hi) {
    ull r; asm("mov.b64 %0, {%1, %2};" : "=l"(r) : "f"(lo), "f"(hi)); return r;
}
__device__ __forceinline__ void upk(ull v, float& lo, float& hi) {
    asm("mov.b64 {%0, %1}, %2;" : "=f"(lo), "=f"(hi) : "l"(v));
}
__device__ __forceinline__ ull fma2(ull a, ull b, ull c) {
    ull d; asm("fma.rn.f32x2 %0, %1, %2, %3;" : "=l"(d) : "l"(a), "l"(b), "l"(c)); return d;
}

// ---------------------------------------------------------------------------
// compose: one layer -> slot s tables.
//  tabW5 : [cls 9][P][9][25] floats   (effective tables incl. bias rules)
//  tabB  : [cls 9][P][9]
//  tabDup: [P][25*9] u64  (cls0, (w,w) pairs, layout [d][k])
//  tabBDup:[P][9]   u64
// valid-q sets: 0 all; 1 T qy>=0; 2 B qy<=0; 3 L qx>=0; 4 R qx<=0;
//               5 TL; 6 TR; 7 BL; 8 BR (intersections).
// ---------------------------------------------------------------------------
__global__ void compose_kernel(const float* __restrict__ W1, const float* __restrict__ b1,
                               const float* __restrict__ W2, const float* __restrict__ b2,
                               float* __restrict__ tabW5, float* __restrict__ tabB,
                               ull* __restrict__ tabDup, ull* __restrict__ tabBDup, int P)
{
    int idx = blockIdx.x * blockDim.x + threadIdx.x;
    if (idx >= 9 * P * 9) return;
    int cls = idx / (P * 9);
    int rem = idx % (P * 9);
    int g = rem / 9, k = rem % 9;

    float T[25];
#pragma unroll
    for (int j = 0; j < 25; j++) T[j] = 0.f;
    float bias = b2[g * 9 + k];

    for (int q = 0; q < 9; q++) {
        int qy = q / 3 - 1, qx = q % 3 - 1;
        bool vy_lo = (qy >= 0), vy_hi = (qy <= 0);
        bool vx_lo = (qx >= 0), vx_hi = (qx <= 0);
        bool in;
        switch (cls) {
            case 0: in = true; break;
            case 1: in = vy_lo; break;
            case 2: in = vy_hi; break;
            case 3: in = vx_lo; break;
            case 4: in = vx_hi; break;
            case 5: in = vy_lo && vx_lo; break;
            case 6: in = vy_lo && vx_hi; break;
            case 7: in = vy_hi && vx_lo; break;
            default: in = vy_hi && vx_hi; break;
        }
        if (!in) continue;
        for (int c = 0; c < HID; c++) {
            float w2 = W2[((size_t)(g * 9 + k) * HID + c) * 9 + q];
            bias += b1[g * HID + c] * w2;
#pragma unroll
            for (int r = 0; r < 9; r++) {
                int ry = r / 3 - 1, rx = r % 3 - 1;
                T[(qy + ry + 2) * 5 + (qx + rx + 2)] += w2 * W1[(size_t)(g * HID + c) * 9 + r];
            }
        }
    }

    float* To = tabW5 + ((size_t)(cls * P + g) * 9 + k) * 25;
#pragma unroll
    for (int j = 0; j < 25; j++) To[j] = T[j];
    tabB[(size_t)(cls * P + g) * 9 + k] = bias;

    if (cls == 0) {
        ull* dd = tabDup + (size_t)g * 225;
#pragma unroll
        for (int d = 0; d < 25; d++) dd[d * 9 + k] = pk(T[d], T[d]);
        tabBDup[(size_t)g * 9 + k] = pk(bias, bias);
    }
}

// ---------------------------------------------------------------------------
// main kernel: interior composed formula, 3 scales fused.
// block = 128 threads, tile 32x32, thread handles 2 rows x 4 cols.
// ---------------------------------------------------------------------------
__global__ __launch_bounds__(128) void smmain_kernel(
    const float* __restrict__ img0, const float* __restrict__ img1p, const float* __restrict__ img2p,
    const float* __restrict__ xin0, const float* __restrict__ xin1, const float* __restrict__ xin2,
    float* __restrict__ out0, float* __restrict__ out1, float* __restrict__ out2,
    const ull* __restrict__ tabDup,   // [s][P][225]
    const ull* __restrict__ tabBDup,  // [s][P][9]
    int nc_in, int P)
{
    __shared__ float simg[36 * 36];
    __shared__ ull   spair[36 * 35];
    __shared__ float sxs[34 * 34];
    __shared__ ull   sWd[225];
    __shared__ ull   sBd[9];

    const int bx = blockIdx.x;
    int s, tile;
    const float *img, *xin;
    float* out;
    if (bx < 16)      { s = 0; tile = bx;      img = img0;  xin = xin0; out = out0; }
    else if (bx < 20) { s = 1; tile = bx - 16; img = img1p; xin = xin1; out = out1; }
    else              { s = 2; tile = bx - 20; img = img2p; xin = xin2; out = out2; }
    const int N = 128 >> s;
    const int tilesX = N / 32;
    const int tx0 = (tile % tilesX) * 32, ty0 = (tile / tilesX) * 32;
    const int o = blockIdx.y, b = blockIdx.z;
    const int tid = threadIdx.x;
    const int pqx = (tid & 7) * 4;
    const int pqy = (tid >> 3) * 2;

    // image tile, halo 2, zero-padded
    const float* ib = img + (size_t)b * N * N;
    for (int idx = tid; idx < 36 * 36; idx += 128) {
        int ly = idx / 36, lx = idx % 36;
        int gy = ty0 - 2 + ly, gx = tx0 - 2 + lx;
        simg[idx] = (gy >= 0 && gy < N && gx >= 0 && gx < N) ? ib[gy * N + gx] : 0.f;
    }
    __syncthreads();
    // packed adjacent-pair image array (built once per block)
    for (int idx = tid; idx < 36 * 35; idx += 128) {
        int ly = idx / 35, lx = idx % 35;
        spair[idx] = pk(simg[ly * 36 + lx], simg[ly * 36 + lx + 1]);
    }

    ull oacc[2][2];
    oacc[0][0] = 0ull; oacc[0][1] = 0ull; oacc[1][0] = 0ull; oacc[1][1] = 0ull;

    for (int i = 0; i < nc_in; i++) {
        const int g = o * nc_in + i;
        __syncthreads();   // protects spair build (iter 0) and sxs/sWd reuse

        const ull* gd = tabDup + ((size_t)s * P + g) * 225;
        for (int idx = tid; idx < 225; idx += 128) sWd[idx] = gd[idx];
        if (tid < 9) sBd[tid] = tabBDup[((size_t)s * P + g) * 9 + tid];

        const float* xb = xin + ((size_t)b * nc_in + i) * N * N;
        for (int idx = tid; idx < 34 * 34; idx += 128) {
            int ly = idx / 34, lx = idx % 34;
            int gy = ty0 - 1 + ly, gx = tx0 - 1 + lx;
            sxs[idx] = (gy >= 0 && gy < N && gx >= 0 && gx < N) ? xb[gy * N + gx] : 0.f;
        }
        __syncthreads();

        // Kf accumulation: acc[k][row][colpair], lanes = 2 adjacent pixels
        ull acc[9][2][2];
#pragma unroll
        for (int k = 0; k < 9; k++) {
            ull bb = sBd[k];
            acc[k][0][0] = bb; acc[k][0][1] = bb; acc[k][1][0] = bb; acc[k][1][1] = bb;
        }

        ull ra[7], rb[7];
        {
            const ull* sp = spair + pqy * 35 + pqx;
#pragma unroll
            for (int c = 0; c < 7; c++) ra[c] = sp[c];
        }
#pragma unroll
        for (int dy = 0; dy < 5; dy++) {
            const ull* sq = spair + (pqy + dy + 1) * 35 + pqx;
#pragma unroll
            for (int c = 0; c < 7; c++) rb[c] = sq[c];
#pragma unroll
            for (int dx = 0; dx < 5; dx++) {
#pragma unroll
                for (int k = 0; k < 9; k++) {
                    ull w = sWd[(dy * 5 + dx) * 9 + k];
                    acc[k][0][0] = fma2(ra[dx],     w, acc[k][0][0]);
                    acc[k][0][1] = fma2(ra[dx + 2], w, acc[k][0][1]);
                    acc[k][1][0] = fma2(rb[dx],     w, acc[k][1][0]);
                    acc[k][1][1] = fma2(rb[dx + 2], w, acc[k][1][1]);
                }
            }
#pragma unroll
            for (int c = 0; c < 7; c++) ra[c] = rb[c];
        }

        // apply per-pixel 3x3 kernel to x patches
        ull xq[4][5];
#pragma unroll
        for (int r = 0; r < 4; r++) {
            const float* xr = sxs + (pqy + r) * 34 + pqx;
            float v0 = xr[0], v1 = xr[1], v2 = xr[2], v3 = xr[3], v4 = xr[4], v5 = xr[5];
            xq[r][0] = pk(v0, v1); xq[r][1] = pk(v1, v2); xq[r][2] = pk(v2, v3);
            xq[r][3] = pk(v3, v4); xq[r][4] = pk(v4, v5);
        }
#pragma unroll
        for (int k = 0; k < 9; k++) {
            const int ky = k / 3, kx = k % 3;
            oacc[0][0] = fma2(acc[k][0][0], xq[ky][kx],         oacc[0][0]);
            oacc[0][1] = fma2(acc[k][0][1], xq[ky][kx + 2],     oacc[0][1]);
            oacc[1][0] = fma2(acc[k][1][0], xq[ky + 1][kx],     oacc[1][0]);
            oacc[1][1] = fma2(acc[k][1][1], xq[ky + 1][kx + 2], oacc[1][1]);
        }
    }

    float* ob = out + ((size_t)b * NC + o) * N * N;
#pragma unroll
    for (int sy = 0; sy < 2; sy++) {
#pragma unroll
        for (int cp = 0; cp < 2; cp++) {
            float lo, hi;
            upk(oacc[sy][cp], lo, hi);
            int row = ty0 + pqy + sy, col = tx0 + pqx + 2 * cp;
            ob[row * N + col]     = elu_f(lo);
            ob[row * N + col + 1] = elu_f(hi);
        }
    }
}

// ---------------------------------------------------------------------------
// border kernel: recompute edge pixels exactly via class tables.
// thread = (border-pixel, o, b); scales fused (508 + 252 + 124 pixels).
// ---------------------------------------------------------------------------
__global__ void border_kernel(
    const float* __restrict__ img0, const float* __restrict__ img1p, const float* __restrict__ img2p,
    const float* __restrict__ xin0, const float* __restrict__ xin1, const float* __restrict__ xin2,
    float* __restrict__ out0, float* __restrict__ out1, float* __restrict__ out2,
    const float* __restrict__ tabW5,  // [s][9][P][9][25]
    const float* __restrict__ tabB,   // [s][9][P][9]
    int nc_in, int P, int total)
{
    int idx = blockIdx.x * blockDim.x + threadIdx.x;
    if (idx >= total) return;
    int bp = idx >> 6;
    int rem = idx & 63;
    int o = rem >> 3, b = rem & 7;

    int s, e;
    if (bp < 508)      { s = 0; e = bp; }
    else if (bp < 760) { s = 1; e = bp - 508; }
    else               { s = 2; e = bp - 760; }
    const float* img = (s == 0) ? img0 : (s == 1) ? img1p : img2p;
    const float* xin = (s == 0) ? xin0 : (s == 1) ? xin1 : xin2;
    float* out = (s == 0) ? out0 : (s == 1) ? out1 : out2;
    const int N = 128 >> s;

    int py, px;
    if (e < N)              { py = 0;     px = e; }
    else if (e < 2 * N)     { py = N - 1; px = e - N; }
    else if (e < 3 * N - 2) { py = e - 2 * N + 1;       px = 0; }
    else                    { py = e - (3 * N - 2) + 1; px = N - 1; }

    bool Tt = (py == 0), Bb = (py == N - 1), Ll = (px == 0), Rr = (px == N - 1);
    int cls = Tt ? (Ll ? 5 : (Rr ? 6 : 1))
                 : (Bb ? (Ll ? 7 : (Rr ? 8 : 2)) : (Ll ? 3 : 4));

    // gather 5x5 image window (zero outside)
    float w[25];
    const float* ibp = img + (size_t)b * N * N;
#pragma unroll
    for (int dy = 0; dy < 5; dy++) {
#pragma unroll
        for (int dx = 0; dx < 5; dx++) {
            int iy = py - 2 + dy, ix = px - 2 + dx;
            w[dy * 5 + dx] = (iy >= 0 && iy < N && ix >= 0 && ix < N) ? ibp[iy * N + ix] : 0.f;
        }
    }

    float accv = 0.f;
    for (int i = 0; i < nc_in; i++) {
        int g = o * nc_in + i;
        const float* tb = tabW5 + (((size_t)(s * 9 + cls) * P + g) * 9) * 25;
        const float* bb = tabB + ((size_t)(s * 9 + cls) * P + g) * 9;
        const float* xb = xin + ((size_t)b * nc_in + i) * N * N;

        float Kf[9];
#pragma unroll
        for (int k = 0; k < 9; k++) Kf[k] = bb[k];
#pragma unroll
        for (int j = 0; j < 25; j++) {
            float v = w[j];
#pragma unroll
            for (int k = 0; k < 9; k++) Kf[k] += tb[k * 25 + j] * v;
        }
#pragma unroll
        for (int k = 0; k < 9; k++) {
            int yy = py + k / 3 - 1, xx = px + k % 3 - 1;
            float xv = (yy >= 0 && yy < N && xx >= 0 && xx < N) ? xb[yy * N + xx] : 0.f;
            accv += Kf[k] * xv;
        }
    }
    out[((size_t)b * NC + o) * N * N + py * N + px] = elu_f(accv);
}

// ---------------------------------------------------------------------------
__global__ void down_kernel(const float* __restrict__ in, float* __restrict__ out,
                            int C, int No)
{
    int idx = blockIdx.x * blockDim.x + threadIdx.x;
    int total = C * No * No;
    if (idx >= total) return;
    int c = idx / (No * No);
    int p = idx % (No * No);
    int h = p / No, w = p % No;
    int Ni = No * 2;
    const float* ib = in + (size_t)c * Ni * Ni;
    float sv = ib[(2 * h) * Ni + 2 * w] + ib[(2 * h) * Ni + 2 * w + 1]
             + ib[(2 * h + 1) * Ni + 2 * w] + ib[(2 * h + 1) * Ni + 2 * w + 1];
    out[idx] = 0.25f * sv;
}

__global__ void combine_kernel(const float* __restrict__ x0,
                               const float* __restrict__ x1,
                               const float* __restrict__ x2,
                               const float* __restrict__ w5, const float* __restrict__ b5,
                               const float* __restrict__ w6, const float* __restrict__ b6,
                               float* __restrict__ out)
{
    int idx = blockIdx.x * blockDim.x + threadIdx.x;
    if (idx >= 8 * 128 * 128) return;
    int b = idx / (128 * 128);
    int p = idx % (128 * 128);
    int h = p / 128, w = p % 128;
    float v[NC];
#pragma unroll
    for (int c = 0; c < NC; c++) {
        v[c] = x0[((size_t)b * NC + c) * 16384 + p]
             + x1[((size_t)b * NC + c) * 4096 + (h >> 1) * 64 + (w >> 1)]
             + x2[((size_t)b * NC + c) * 1024 + (h >> 2) * 32 + (w >> 2)];
    }
    float accv = b6[0];
#pragma unroll
    for (int o = 0; o < NC; o++) {
        float y = b5[o];
#pragma unroll
        for (int c = 0; c < NC; c++) y += w5[o * NC + c] * v[c];
        y = elu_f(y);
        accv += w6[o] * y;
    }
    out[idx] = accv;
}

// ---------------------------------------------------------------------------
extern "C" void kernel_launch(void* const* d_in, const int* in_sizes, int n_in,
                              void* d_out, int out_size)
{
    const float* image = (const float*)d_in[0];
    const float* x_in  = (const float*)d_in[1];
    const float* iW1   = (const float*)d_in[2];
    const float* ib1   = (const float*)d_in[3];
    const float* iW2   = (const float*)d_in[4];
    const float* ib2   = (const float*)d_in[5];
    const float* bW1   = (const float*)d_in[6];
    const float* bb1   = (const float*)d_in[7];
    const float* bW2   = (const float*)d_in[8];
    const float* bb2   = (const float*)d_in[9];
    const float* w5    = (const float*)d_in[10];
    const float* b5    = (const float*)d_in[11];
    const float* w6    = (const float*)d_in[12];
    const float* b6    = (const float*)d_in[13];

    float* base;
    cudaGetSymbolAddress((void**)&base, g_buf);
    float* img1 = base;                   // 32768
    float* img2 = img1 + 32768;           // 8192
    float* x0a  = img2 + 8192;            // 1048576
    float* x0b  = x0a + 1048576;
    float* x1a  = x0b + 1048576;          // 262144
    float* x1b  = x1a + 262144;
    float* x2a  = x1b + 262144;           // 65536
    float* x2b  = x2a + 65536;
    float* tabW5 = x2b + 65536;           // 3*9*64*9*25 = 388800
    float* tabB  = tabW5 + 388800;        // 3*9*64*9 = 15552
    ull*   tabDup  = (ull*)(tabB + 15552);    // 3*64*225 = 43200 ull
    ull*   tabBDup = tabDup + 43200;          // 3*64*9   = 1728 ull

    const size_t W5_S = 9 * 64 * 9 * 25;   // per-scale strides (P=64 slots)
    const size_t B_S  = 9 * 64 * 9;
    const size_t D_S  = 64 * 225;
    const size_t BD_S = 64 * 9;

    // image pyramid
    down_kernel<<<(8 * 64 * 64 + 255) / 256, 256>>>(image, img1, 8, 64);
    down_kernel<<<(8 * 32 * 32 + 255) / 256, 256>>>(img1, img2, 8, 32);

    // ---- init block (P=8, nc_in=1, full-res only) ----
    compose_kernel<<<(9 * 8 * 9 + 127) / 128, 128>>>(iW1, ib1, iW2, ib2,
        tabW5, tabB, tabDup, tabBDup, 8);
    smmain_kernel<<<dim3(16, 8, 8), 128>>>(image, img1, img2,
        x_in, x_in, x_in, x0a, x0a, x0a, tabDup, tabBDup, 1, 8);
    border_kernel<<<(508 * 64 + 127) / 128, 128>>>(image, img1, img2,
        x_in, x_in, x_in, x0a, x0a, x0a, tabW5, tabB, 1, 8, 508 * 64);

    // downsample x (after border fix)
    down_kernel<<<(64 * 64 * 64 + 255) / 256, 256>>>(x0a, x1a, 64, 64);
    down_kernel<<<(64 * 32 * 32 + 255) / 256, 256>>>(x1a, x2a, 64, 32);

    float *xc = x0a, *xn = x0b;
    float *x1c = x1a, *x1n = x1b;
    float *x2c = x2a, *x2n = x2b;

    for (int t = 0; t < 4; t++) {
        for (int sIdx = 0; sIdx < 3; sIdx++) {
            int l = 3 * t + sIdx;
            compose_kernel<<<(9 * 64 * 9 + 127) / 128, 128>>>(
                bW1 + (size_t)l * 1280 * 9, bb1 + (size_t)l * 1280,
                bW2 + (size_t)l * 576 * 180, bb2 + (size_t)l * 576,
                tabW5 + sIdx * W5_S, tabB + sIdx * B_S,
                tabDup + sIdx * D_S, tabBDup + sIdx * BD_S, 64);
        }
        smmain_kernel<<<dim3(21, 8, 8), 128>>>(image, img1, img2,
            xc, x1c, x2c, xn, x1n, x2n, tabDup, tabBDup, 8, 64);
        border_kernel<<<(884 * 64 + 127) / 128, 128>>>(image, img1, img2,
            xc, x1c, x2c, xn, x1n, x2n, tabW5, tabB, 8, 64, 884 * 64);
        { float* tp = xc;  xc = xn;   xn = tp; }
        { float* tp = x1c; x1c = x1n; x1n = tp; }
        { float* tp = x2c; x2c = x2n; x2n = tp; }
    }

    combine_kernel<<<(8 * 128 * 128 + 255) / 256, 256>>>(
        xc, x1c, x2c, w5, b5, w6, b6, (float*)d_out);
}

// round 5
// speedup vs baseline: 8.0559x; 1.2755x over previous
#include <cuda_runtime.h>
#include <math.h>

// ---------------------------------------------------------------------------
// SMModel — composed-5x5, packed f32x2, k-grouped accumulators.
//  * compose (ONE upfront launch): per (layer 13, cls 9, g, k) effective 5x5
//    tables; interior tables also as duplicated (w,w) u64 pairs.
//  * smmain: interior formula, 3 scales fused, border blocks fused into the
//    same launch (main blocks skip border-pixel stores).
//  * k split into 3 groups of 3 -> acc regs 72 -> 24, higher occupancy.
// ---------------------------------------------------------------------------

#define NC    8
#define HID   20

typedef unsigned long long ull;

// floats: img1 32768 | img2 8192 | x0a/b 2*1048576 | x1a/b 2*262144 |
// x2a/b 2*65536 | tabW5 13*129600 | tabB 13*5184 | tabDup 13*14400 ull |
// tabBDup 13*576 ull
__device__ float g_buf[4935040];

__device__ __forceinline__ float elu_f(float v) {
    return v > 0.f ? v : (expf(v) - 1.f);
}
__device__ __forceinline__ ull pk(float lo, float hi) {
    ull r; asm("mov.b64 %0, {%1, %2};" : "=l"(r) : "f"(lo), "f"(hi)); return r;
}
__device__ __forceinline__ void upk(ull v, float& lo, float& hi) {
    asm("mov.b64 {%0, %1}, %2;" : "=f"(lo), "=f"(hi) : "l"(v));
}
__device__ __forceinline__ ull fma2(ull a, ull b, ull c) {
    ull d; asm("fma.rn.f32x2 %0, %1, %2, %3;" : "=l"(d) : "l"(a), "l"(b), "l"(c)); return d;
}

// ---------------------------------------------------------------------------
// compose: ALL 13 layers in one launch.
// slot l: l=0 init (P=8, g<8), l=1..12 blk layer l-1 (P=64).
// tabW5[l][cls9][64][9][25], tabB[l][cls9][64][9],
// tabDup[l][64][25*9] (cls0 dup pairs), tabBDup[l][64][9].
// ---------------------------------------------------------------------------
__global__ void compose_kernel(
    const float* __restrict__ iW1, const float* __restrict__ ib1,
    const float* __restrict__ iW2, const float* __restrict__ ib2,
    const float* __restrict__ bW1, const float* __restrict__ bb1,
    const float* __restrict__ bW2, const float* __restrict__ bb2,
    float* __restrict__ tabW5, float* __restrict__ tabB,
    ull* __restrict__ tabDup, ull* __restrict__ tabBDup)
{
    int idx = blockIdx.x * blockDim.x + threadIdx.x;
    if (idx >= 13 * 5184) return;
    int l = idx / 5184;
    int r0 = idx % 5184;
    int cls = r0 / 576;
    int g = (r0 % 576) / 9, k = r0 % 9;
    if (l == 0 && g >= 8) return;

    const float *W1, *b1, *W2, *b2;
    if (l == 0) { W1 = iW1; b1 = ib1; W2 = iW2; b2 = ib2; }
    else {
        int m = l - 1;
        W1 = bW1 + (size_t)m * 1280 * 9;  b1 = bb1 + (size_t)m * 1280;
        W2 = bW2 + (size_t)m * 576 * 180; b2 = bb2 + (size_t)m * 576;
    }

    float T[25];
#pragma unroll
    for (int j = 0; j < 25; j++) T[j] = 0.f;
    float bias = b2[g * 9 + k];

    for (int q = 0; q < 9; q++) {
        int qy = q / 3 - 1, qx = q % 3 - 1;
        bool vyl = (qy >= 0), vyh = (qy <= 0), vxl = (qx >= 0), vxh = (qx <= 0);
        bool in;
        switch (cls) {
            case 0: in = true; break;
            case 1: in = vyl; break;
            case 2: in = vyh; break;
            case 3: in = vxl; break;
            case 4: in = vxh; break;
            case 5: in = vyl && vxl; break;
            case 6: in = vyl && vxh; break;
            case 7: in = vyh && vxl; break;
            default: in = vyh && vxh; break;
        }
        if (!in) continue;
        for (int c = 0; c < HID; c++) {
            float w2 = W2[((size_t)(g * 9 + k) * HID + c) * 9 + q];
            bias += b1[g * HID + c] * w2;
#pragma unroll
            for (int r = 0; r < 9; r++) {
                int ry = r / 3 - 1, rx = r % 3 - 1;
                T[(qy + ry + 2) * 5 + (qx + rx + 2)] += w2 * W1[(size_t)(g * HID + c) * 9 + r];
            }
        }
    }

    float* To = tabW5 + (size_t)l * 129600 + ((size_t)(cls * 64 + g) * 9 + k) * 25;
#pragma unroll
    for (int j = 0; j < 25; j++) To[j] = T[j];
    tabB[(size_t)l * 5184 + (size_t)(cls * 64 + g) * 9 + k] = bias;

    if (cls == 0) {
        ull* dd = tabDup + (size_t)l * 14400 + (size_t)g * 225;
#pragma unroll
        for (int d = 0; d < 25; d++) dd[d * 9 + k] = pk(T[d], T[d]);
        tabBDup[(size_t)l * 576 + g * 9 + k] = pk(bias, bias);
    }
}

// ---------------------------------------------------------------------------
// main + border fused.
// mode 0 (init): grid.x = 16 main (full only) + 4 border
// mode 1 (blk):  grid.x = 21 main (16 full,4 mid,1 small) + 7 border
// ---------------------------------------------------------------------------
__global__ __launch_bounds__(128) void smmain_kernel(
    const float* __restrict__ img0, const float* __restrict__ img1p, const float* __restrict__ img2p,
    const float* __restrict__ xin0, const float* __restrict__ xin1, const float* __restrict__ xin2,
    float* __restrict__ out0, float* __restrict__ out1, float* __restrict__ out2,
    const ull* __restrict__ tabDup, const ull* __restrict__ tabBDup,
    const float* __restrict__ tabW5, const float* __restrict__ tabB,
    int nc_in, int slotBase, int mode)
{
    const int bx = blockIdx.x;
    const int o = blockIdx.y, b = blockIdx.z;
    const int tid = threadIdx.x;
    const int mainX = (mode == 0) ? 16 : 21;

    if (bx >= mainX) {
        // ---------------- border path ----------------
        int bp = (bx - mainX) * 128 + tid;
        int limit = (mode == 0) ? 508 : 884;
        if (bp >= limit) return;
        int s, e;
        if (bp < 508)      { s = 0; e = bp; }
        else if (bp < 760) { s = 1; e = bp - 508; }
        else               { s = 2; e = bp - 760; }
        const float* img = (s == 0) ? img0 : (s == 1) ? img1p : img2p;
        const float* xin = (s == 0) ? xin0 : (s == 1) ? xin1 : xin2;
        float* out = (s == 0) ? out0 : (s == 1) ? out1 : out2;
        const int N = 128 >> s;
        const int slot = slotBase + s;

        int py, px;
        if (e < N)              { py = 0;     px = e; }
        else if (e < 2 * N)     { py = N - 1; px = e - N; }
        else if (e < 3 * N - 2) { py = e - 2 * N + 1;       px = 0; }
        else                    { py = e - (3 * N - 2) + 1; px = N - 1; }

        bool Tt = (py == 0), Bb = (py == N - 1), Ll = (px == 0), Rr = (px == N - 1);
        int cls = Tt ? (Ll ? 5 : (Rr ? 6 : 1))
                     : (Bb ? (Ll ? 7 : (Rr ? 8 : 2)) : (Ll ? 3 : 4));

        float w[25];
        const float* ibp = img + (size_t)b * N * N;
#pragma unroll
        for (int dy = 0; dy < 5; dy++)
#pragma unroll
            for (int dx = 0; dx < 5; dx++) {
                int iy = py - 2 + dy, ix = px - 2 + dx;
                w[dy * 5 + dx] = (iy >= 0 && iy < N && ix >= 0 && ix < N) ? ibp[iy * N + ix] : 0.f;
            }

        float accv = 0.f;
        for (int i = 0; i < nc_in; i++) {
            int g = o * nc_in + i;
            const float* tb = tabW5 + (size_t)slot * 129600 + ((size_t)(cls * 64 + g) * 9) * 25;
            const float* bb = tabB + (size_t)slot * 5184 + (size_t)(cls * 64 + g) * 9;
            const float* xb = xin + ((size_t)b * nc_in + i) * N * N;
            float Kf[9];
#pragma unroll
            for (int k = 0; k < 9; k++) Kf[k] = bb[k];
#pragma unroll
            for (int j = 0; j < 25; j++) {
                float v = w[j];
#pragma unroll
                for (int k = 0; k < 9; k++) Kf[k] += tb[k * 25 + j] * v;
            }
#pragma unroll
            for (int k = 0; k < 9; k++) {
                int yy = py + k / 3 - 1, xx = px + k % 3 - 1;
                float xv = (yy >= 0 && yy < N && xx >= 0 && xx < N) ? xb[yy * N + xx] : 0.f;
                accv += Kf[k] * xv;
            }
        }
        out[((size_t)b * NC + o) * N * N + py * N + px] = elu_f(accv);
        return;
    }

    // ---------------- main (interior) path ----------------
    __shared__ float simg[36 * 36];
    __shared__ ull   spair[36 * 35];
    __shared__ float sxs[34 * 34];
    __shared__ ull   sWd[225];
    __shared__ ull   sBd[9];

    int s, tile;
    const float *img, *xin;
    float* out;
    if (bx < 16)      { s = 0; tile = bx;      img = img0;  xin = xin0; out = out0; }
    else if (bx < 20) { s = 1; tile = bx - 16; img = img1p; xin = xin1; out = out1; }
    else              { s = 2; tile = bx - 20; img = img2p; xin = xin2; out = out2; }
    const int N = 128 >> s;
    const int tilesX = N / 32;
    const int tx0 = (tile % tilesX) * 32, ty0 = (tile / tilesX) * 32;
    const int slot = slotBase + s;
    const int pqx = (tid & 7) * 4;
    const int pqy = (tid >> 3) * 2;

    const float* ib = img + (size_t)b * N * N;
    for (int idx = tid; idx < 36 * 36; idx += 128) {
        int ly = idx / 36, lx = idx % 36;
        int gy = ty0 - 2 + ly, gx = tx0 - 2 + lx;
        simg[idx] = (gy >= 0 && gy < N && gx >= 0 && gx < N) ? ib[gy * N + gx] : 0.f;
    }
    __syncthreads();
    for (int idx = tid; idx < 36 * 35; idx += 128) {
        int ly = idx / 35, lx = idx % 35;
        spair[idx] = pk(simg[ly * 36 + lx], simg[ly * 36 + lx + 1]);
    }

    ull oacc[2][2];
    oacc[0][0] = 0ull; oacc[0][1] = 0ull; oacc[1][0] = 0ull; oacc[1][1] = 0ull;

#pragma unroll 1
    for (int i = 0; i < nc_in; i++) {
        const int g = o * nc_in + i;
        __syncthreads();   // spair build done (iter 0); sWd/sxs reuse safe

        const ull* gd = tabDup + (size_t)slot * 14400 + (size_t)g * 225;
        for (int idx = tid; idx < 225; idx += 128) sWd[idx] = gd[idx];
        if (tid < 9) sBd[tid] = tabBDup[(size_t)slot * 576 + g * 9 + tid];

        const float* xb = xin + ((size_t)b * nc_in + i) * N * N;
        for (int idx = tid; idx < 34 * 34; idx += 128) {
            int ly = idx / 34, lx = idx % 34;
            int gy = ty0 - 1 + ly, gx = tx0 - 1 + lx;
            sxs[idx] = (gy >= 0 && gy < N && gx >= 0 && gx < N) ? xb[gy * N + gx] : 0.f;
        }
        __syncthreads();

#pragma unroll 1
        for (int kg = 0; kg < 3; kg++) {
            // x pairs for rows pqy+kg, pqy+kg+1
            ull xq[2][5];
#pragma unroll
            for (int rr = 0; rr < 2; rr++) {
                const float* xr = sxs + (pqy + kg + rr) * 34 + pqx;
                float v0 = xr[0], v1 = xr[1], v2 = xr[2], v3 = xr[3], v4 = xr[4], v5 = xr[5];
                xq[rr][0] = pk(v0, v1); xq[rr][1] = pk(v1, v2); xq[rr][2] = pk(v2, v3);
                xq[rr][3] = pk(v3, v4); xq[rr][4] = pk(v4, v5);
            }

            ull acc[3][2][2];
#pragma unroll
            for (int j = 0; j < 3; j++) {
                ull bb = sBd[3 * kg + j];
                acc[j][0][0] = bb; acc[j][0][1] = bb; acc[j][1][0] = bb; acc[j][1][1] = bb;
            }

            const ull* wbase = sWd + 3 * kg;
            ull ra[7], rb[7];
            {
                const ull* sp = spair + pqy * 35 + pqx;
#pragma unroll
                for (int c = 0; c < 7; c++) ra[c] = sp[c];
            }
#pragma unroll
            for (int dy = 0; dy < 5; dy++) {
                const ull* sq = spair + (pqy + dy + 1) * 35 + pqx;
#pragma unroll
                for (int c = 0; c < 7; c++) rb[c] = sq[c];
#pragma unroll
                for (int dx = 0; dx < 5; dx++) {
#pragma unroll
                    for (int j = 0; j < 3; j++) {
                        ull w = wbase[(dy * 5 + dx) * 9 + j];
                        acc[j][0][0] = fma2(ra[dx],     w, acc[j][0][0]);
                        acc[j][0][1] = fma2(ra[dx + 2], w, acc[j][0][1]);
                        acc[j][1][0] = fma2(rb[dx],     w, acc[j][1][0]);
                        acc[j][1][1] = fma2(rb[dx + 2], w, acc[j][1][1]);
                    }
                }
#pragma unroll
                for (int c = 0; c < 7; c++) ra[c] = rb[c];
            }

#pragma unroll
            for (int j = 0; j < 3; j++) {
                oacc[0][0] = fma2(acc[j][0][0], xq[0][j],     oacc[0][0]);
                oacc[0][1] = fma2(acc[j][0][1], xq[0][j + 2], oacc[0][1]);
                oacc[1][0] = fma2(acc[j][1][0], xq[1][j],     oacc[1][0]);
                oacc[1][1] = fma2(acc[j][1][1], xq[1][j + 2], oacc[1][1]);
            }
        }
    }

    float* ob = out + ((size_t)b * NC + o) * N * N;
#pragma unroll
    for (int sy = 0; sy < 2; sy++) {
#pragma unroll
        for (int cp = 0; cp < 2; cp++) {
            float lo, hi;
            upk(oacc[sy][cp], lo, hi);
            int row = ty0 + pqy + sy, col = tx0 + pqx + 2 * cp;
            if (row > 0 && row < N - 1) {
                if (col > 0 && col < N - 1)         ob[row * N + col]     = elu_f(lo);
                if (col + 1 > 0 && col + 1 < N - 1) ob[row * N + col + 1] = elu_f(hi);
            }
        }
    }
}

// ---------------------------------------------------------------------------
__global__ void down_kernel(const float* __restrict__ in, float* __restrict__ out,
                            int C, int No)
{
    int idx = blockIdx.x * blockDim.x + threadIdx.x;
    int total = C * No * No;
    if (idx >= total) return;
    int c = idx / (No * No);
    int p = idx % (No * No);
    int h = p / No, w = p % No;
    int Ni = No * 2;
    const float* ib = in + (size_t)c * Ni * Ni;
    float sv = ib[(2 * h) * Ni + 2 * w] + ib[(2 * h) * Ni + 2 * w + 1]
             + ib[(2 * h + 1) * Ni + 2 * w] + ib[(2 * h + 1) * Ni + 2 * w + 1];
    out[idx] = 0.25f * sv;
}

__global__ void combine_kernel(const float* __restrict__ x0,
                               const float* __restrict__ x1,
                               const float* __restrict__ x2,
                               const float* __restrict__ w5, const float* __restrict__ b5,
                               const float* __restrict__ w6, const float* __restrict__ b6,
                               float* __restrict__ out)
{
    int idx = blockIdx.x * blockDim.x + threadIdx.x;
    if (idx >= 8 * 128 * 128) return;
    int b = idx / (128 * 128);
    int p = idx % (128 * 128);
    int h = p / 128, w = p % 128;
    float v[NC];
#pragma unroll
    for (int c = 0; c < NC; c++) {
        v[c] = x0[((size_t)b * NC + c) * 16384 + p]
             + x1[((size_t)b * NC + c) * 4096 + (h >> 1) * 64 + (w >> 1)]
             + x2[((size_t)b * NC + c) * 1024 + (h >> 2) * 32 + (w >> 2)];
    }
    float accv = b6[0];
#pragma unroll
    for (int o = 0; o < NC; o++) {
        float y = b5[o];
#pragma unroll
        for (int c = 0; c < NC; c++) y += w5[o * NC + c] * v[c];
        y = elu_f(y);
        accv += w6[o] * y;
    }
    out[idx] = accv;
}

// ---------------------------------------------------------------------------
extern "C" void kernel_launch(void* const* d_in, const int* in_sizes, int n_in,
                              void* d_out, int out_size)
{
    const float* image = (const float*)d_in[0];
    const float* x_in  = (const float*)d_in[1];
    const float* iW1   = (const float*)d_in[2];
    const float* ib1   = (const float*)d_in[3];
    const float* iW2   = (const float*)d_in[4];
    const float* ib2   = (const float*)d_in[5];
    const float* bW1   = (const float*)d_in[6];
    const float* bb1   = (const float*)d_in[7];
    const float* bW2   = (const float*)d_in[8];
    const float* bb2   = (const float*)d_in[9];
    const float* w5    = (const float*)d_in[10];
    const float* b5    = (const float*)d_in[11];
    const float* w6    = (const float*)d_in[12];
    const float* b6    = (const float*)d_in[13];

    float* base;
    cudaGetSymbolAddress((void**)&base, g_buf);
    float* img1 = base;                    // 32768
    float* img2 = img1 + 32768;            // 8192
    float* x0a  = img2 + 8192;             // 1048576
    float* x0b  = x0a + 1048576;
    float* x1a  = x0b + 1048576;           // 262144
    float* x1b  = x1a + 262144;
    float* x2a  = x1b + 262144;            // 65536
    float* x2b  = x2a + 65536;
    float* tabW5 = x2b + 65536;            // 13*129600
    float* tabB  = tabW5 + 13 * 129600;    // 13*5184
    ull*   tabDup  = (ull*)(tabB + 13 * 5184);   // 13*14400 ull
    ull*   tabBDup = tabDup + 13 * 14400;        // 13*576 ull

    // all tables upfront (x-independent)
    compose_kernel<<<(13 * 5184 + 127) / 128, 128>>>(
        iW1, ib1, iW2, ib2, bW1, bb1, bW2, bb2, tabW5, tabB, tabDup, tabBDup);

    // image pyramid
    down_kernel<<<(8 * 64 * 64 + 255) / 256, 256>>>(image, img1, 8, 64);
    down_kernel<<<(8 * 32 * 32 + 255) / 256, 256>>>(img1, img2, 8, 32);

    // init block (slot 0, nc_in=1, full-res only) with fused border
    smmain_kernel<<<dim3(20, 8, 8), 128>>>(image, img1, img2,
        x_in, x_in, x_in, x0a, x0a, x0a, tabDup, tabBDup, tabW5, tabB, 1, 0, 0);

    // downsample x
    down_kernel<<<(64 * 64 * 64 + 255) / 256, 256>>>(x0a, x1a, 64, 64);
    down_kernel<<<(64 * 32 * 32 + 255) / 256, 256>>>(x1a, x2a, 64, 32);

    float *xc = x0a, *xn = x0b;
    float *x1c = x1a, *x1n = x1b;
    float *x2c = x2a, *x2n = x2b;

    for (int t = 0; t < 4; t++) {
        smmain_kernel<<<dim3(28, 8, 8), 128>>>(image, img1, img2,
            xc, x1c, x2c, xn, x1n, x2n, tabDup, tabBDup, tabW5, tabB,
            8, 1 + 3 * t, 1);
        { float* tp = xc;  xc = xn;   xn = tp; }
        { float* tp = x1c; x1c = x1n; x1n = tp; }
        { float* tp = x2c; x2c = x2n; x2n = tp; }
    }

    combine_kernel<<<(8 * 128 * 128 + 255) / 256, 256>>>(
        xc, x1c, x2c, w5, b5, w6, b6, (float*)d_out);
}

// round 6
// speedup vs baseline: 8.3885x; 1.0413x over previous
#include <cuda_runtime.h>
#include <math.h>

// ---------------------------------------------------------------------------
// SMModel — composed-5x5, packed f32x2, channel-group phasing, vector LDS.
// ---------------------------------------------------------------------------

#define NC    8
#define HID   20
#define CHG   4

typedef unsigned long long ull;

__device__ __align__(16) float g_buf[5064832];

__device__ __forceinline__ float elu_f(float v) {
    return v > 0.f ? v : (expf(v) - 1.f);
}
__device__ __forceinline__ ull pk(float lo, float hi) {
    ull r; asm("mov.b64 %0, {%1, %2};" : "=l"(r) : "f"(lo), "f"(hi)); return r;
}
__device__ __forceinline__ void upk(ull v, float& lo, float& hi) {
    asm("mov.b64 {%0, %1}, %2;" : "=f"(lo), "=f"(hi) : "l"(v));
}
__device__ __forceinline__ ull fma2(ull a, ull b, ull c) {
    ull d; asm("fma.rn.f32x2 %0, %1, %2, %3;" : "=l"(d) : "l"(a), "l"(b), "l"(c)); return d;
}

// ---------------------------------------------------------------------------
// compose: ALL 13 layers, one launch.
// tabW5[l][cls9][64][9][25] f, tabB[l][cls9][64][9] f,
// tabDup[l][64][25*12] ull (pairs, slot d*12+kg*4+j), tabBDup[l][64][12] ull.
// ---------------------------------------------------------------------------
__global__ void compose_kernel(
    const float* __restrict__ iW1, const float* __restrict__ ib1,
    const float* __restrict__ iW2, const float* __restrict__ ib2,
    const float* __restrict__ bW1, const float* __restrict__ bb1,
    const float* __restrict__ bW2, const float* __restrict__ bb2,
    float* __restrict__ tabW5, float* __restrict__ tabB,
    ull* __restrict__ tabDup, ull* __restrict__ tabBDup)
{
    int idx = blockIdx.x * blockDim.x + threadIdx.x;
    if (idx >= 13 * 5184) return;
    int l = idx / 5184;
    int r0 = idx % 5184;
    int cls = r0 / 576;
    int g = (r0 % 576) / 9, k = r0 % 9;
    if (l == 0 && g >= 8) return;

    const float *W1, *b1, *W2, *b2;
    if (l == 0) { W1 = iW1; b1 = ib1; W2 = iW2; b2 = ib2; }
    else {
        int m = l - 1;
        W1 = bW1 + (size_t)m * 1280 * 9;  b1 = bb1 + (size_t)m * 1280;
        W2 = bW2 + (size_t)m * 576 * 180; b2 = bb2 + (size_t)m * 576;
    }

    float T[25];
#pragma unroll
    for (int j = 0; j < 25; j++) T[j] = 0.f;
    float bias = b2[g * 9 + k];

    for (int q = 0; q < 9; q++) {
        int qy = q / 3 - 1, qx = q % 3 - 1;
        bool vyl = (qy >= 0), vyh = (qy <= 0), vxl = (qx >= 0), vxh = (qx <= 0);
        bool in;
        switch (cls) {
            case 0: in = true; break;
            case 1: in = vyl; break;
            case 2: in = vyh; break;
            case 3: in = vxl; break;
            case 4: in = vxh; break;
            case 5: in = vyl && vxl; break;
            case 6: in = vyl && vxh; break;
            case 7: in = vyh && vxl; break;
            default: in = vyh && vxh; break;
        }
        if (!in) continue;
        for (int c = 0; c < HID; c++) {
            float w2 = W2[((size_t)(g * 9 + k) * HID + c) * 9 + q];
            bias += b1[g * HID + c] * w2;
#pragma unroll
            for (int r = 0; r < 9; r++) {
                int ry = r / 3 - 1, rx = r % 3 - 1;
                T[(qy + ry + 2) * 5 + (qx + rx + 2)] += w2 * W1[(size_t)(g * HID + c) * 9 + r];
            }
        }
    }

    float* To = tabW5 + (size_t)l * 129600 + ((size_t)(cls * 64 + g) * 9 + k) * 25;
#pragma unroll
    for (int j = 0; j < 25; j++) To[j] = T[j];
    tabB[(size_t)l * 5184 + (size_t)(cls * 64 + g) * 9 + k] = bias;

    if (cls == 0) {
        ull* dd = tabDup + (size_t)l * 19200 + (size_t)g * 300;
        int kg = k / 3, j = k % 3;
#pragma unroll
        for (int d = 0; d < 25; d++) dd[d * 12 + kg * 4 + j] = pk(T[d], T[d]);
        tabBDup[(size_t)l * 768 + g * 12 + kg * 4 + j] = pk(bias, bias);
    }
}

// ---------------------------------------------------------------------------
__device__ __forceinline__ void load_row(const ull* __restrict__ spair,
                                         int row, int pqx, ull (&R)[7])
{
    const ull* base = spair + row * 36 + pqx;
    ulonglong2 t0 = *reinterpret_cast<const ulonglong2*>(base);
    ulonglong2 t1 = *reinterpret_cast<const ulonglong2*>(base + 2);
    ulonglong2 t2 = *reinterpret_cast<const ulonglong2*>(base + 4);
    R[0] = t0.x; R[1] = t0.y; R[2] = t1.x; R[3] = t1.y;
    R[4] = t2.x; R[5] = t2.y; R[6] = base[6];
}

__device__ __forceinline__ void conv_step(const ull* __restrict__ wd, int kg, int dy,
                                          const ull (&R)[7], const ull (&S)[7],
                                          ull (&acc)[3][2][2])
{
#pragma unroll
    for (int dx = 0; dx < 5; dx++) {
        const ull* wp = wd + (dy * 5 + dx) * 12 + kg * 4;
        ulonglong2 w01 = *reinterpret_cast<const ulonglong2*>(wp);
        ull w2v = wp[2];
        ull wv;
#pragma unroll
        for (int j = 0; j < 3; j++) {
            wv = (j == 0) ? w01.x : (j == 1) ? w01.y : w2v;
            acc[j][0][0] = fma2(R[dx],     wv, acc[j][0][0]);
            acc[j][0][1] = fma2(R[dx + 2], wv, acc[j][0][1]);
            acc[j][1][0] = fma2(S[dx],     wv, acc[j][1][0]);
            acc[j][1][1] = fma2(S[dx + 2], wv, acc[j][1][1]);
        }
    }
}

// ---------------------------------------------------------------------------
// main + border fused; dynamic smem 45120 bytes.
// ---------------------------------------------------------------------------
__global__ __launch_bounds__(128) void smmain_kernel(
    const float* __restrict__ img0, const float* __restrict__ img1p, const float* __restrict__ img2p,
    const float* __restrict__ xin0, const float* __restrict__ xin1, const float* __restrict__ xin2,
    float* __restrict__ out0, float* __restrict__ out1, float* __restrict__ out2,
    const ull* __restrict__ tabDup, const ull* __restrict__ tabBDup,
    const float* __restrict__ tabW5, const float* __restrict__ tabB,
    int nc_in, int slotBase, int mode)
{
    const int bx = blockIdx.x;
    const int o = blockIdx.y, b = blockIdx.z;
    const int tid = threadIdx.x;
    const int mainX = (mode == 0) ? 16 : 21;

    if (bx >= mainX) {
        // ---------------- border path ----------------
        int bp = (bx - mainX) * 128 + tid;
        int limit = (mode == 0) ? 508 : 884;
        if (bp >= limit) return;
        int s, e;
        if (bp < 508)      { s = 0; e = bp; }
        else if (bp < 760) { s = 1; e = bp - 508; }
        else               { s = 2; e = bp - 760; }
        const float* img = (s == 0) ? img0 : (s == 1) ? img1p : img2p;
        const float* xin = (s == 0) ? xin0 : (s == 1) ? xin1 : xin2;
        float* out = (s == 0) ? out0 : (s == 1) ? out1 : out2;
        const int N = 128 >> s;
        const int slot = slotBase + s;

        int py, px;
        if (e < N)              { py = 0;     px = e; }
        else if (e < 2 * N)     { py = N - 1; px = e - N; }
        else if (e < 3 * N - 2) { py = e - 2 * N + 1;       px = 0; }
        else                    { py = e - (3 * N - 2) + 1; px = N - 1; }

        bool Tt = (py == 0), Bb = (py == N - 1), Ll = (px == 0), Rr = (px == N - 1);
        int cls = Tt ? (Ll ? 5 : (Rr ? 6 : 1))
                     : (Bb ? (Ll ? 7 : (Rr ? 8 : 2)) : (Ll ? 3 : 4));

        float w[25];
        const float* ibp = img + (size_t)b * N * N;
#pragma unroll
        for (int dy = 0; dy < 5; dy++)
#pragma unroll
            for (int dx = 0; dx < 5; dx++) {
                int iy = py - 2 + dy, ix = px - 2 + dx;
                w[dy * 5 + dx] = (iy >= 0 && iy < N && ix >= 0 && ix < N) ? ibp[iy * N + ix] : 0.f;
            }

        float accv = 0.f;
        for (int i = 0; i < nc_in; i++) {
            int g = o * nc_in + i;
            const float* tb = tabW5 + (size_t)slot * 129600 + ((size_t)(cls * 64 + g) * 9) * 25;
            const float* bb = tabB + (size_t)slot * 5184 + (size_t)(cls * 64 + g) * 9;
            const float* xb = xin + ((size_t)b * nc_in + i) * N * N;
            float Kf[9];
#pragma unroll
            for (int k = 0; k < 9; k++) Kf[k] = bb[k];
#pragma unroll
            for (int j = 0; j < 25; j++) {
                float v = w[j];
#pragma unroll
                for (int k = 0; k < 9; k++) Kf[k] += tb[k * 25 + j] * v;
            }
#pragma unroll
            for (int k = 0; k < 9; k++) {
                int yy = py + k / 3 - 1, xx = px + k % 3 - 1;
                float xv = (yy >= 0 && yy < N && xx >= 0 && xx < N) ? xb[yy * N + xx] : 0.f;
                accv += Kf[k] * xv;
            }
        }
        out[((size_t)b * NC + o) * N * N + py * N + px] = elu_f(accv);
        return;
    }

    // ---------------- main (interior) path ----------------
    extern __shared__ __align__(16) char smraw[];
    float* simg  = (float*)smraw;                 // 36*36 f        = 5184 B
    ull*   spair = (ull*)(smraw + 5184);          // 36*36 ull      = 10368 B
    float* sxs   = (float*)(smraw + 15552);       // 4 * 34*36 f    = 19584 B
    ull*   sWd   = (ull*)(smraw + 35136);         // 4 * 300 ull    = 9600 B
    ull*   sBd   = (ull*)(smraw + 44736);         // 4 * 12 ull     = 384 B

    int s, tile;
    const float *img, *xin;
    float* out;
    if (bx < 16)      { s = 0; tile = bx;      img = img0;  xin = xin0; out = out0; }
    else if (bx < 20) { s = 1; tile = bx - 16; img = img1p; xin = xin1; out = out1; }
    else              { s = 2; tile = bx - 20; img = img2p; xin = xin2; out = out2; }
    const int N = 128 >> s;
    const int tilesX = N / 32;
    const int tx0 = (tile % tilesX) * 32, ty0 = (tile / tilesX) * 32;
    const int slot = slotBase + s;
    const int pqx = (tid & 7) * 4;
    const int pqy = (tid >> 3) * 2;

    const float* ib = img + (size_t)b * N * N;
    for (int idx = tid; idx < 36 * 36; idx += 128) {
        int ly = idx / 36, lx = idx % 36;
        int gy = ty0 - 2 + ly, gx = tx0 - 2 + lx;
        simg[idx] = (gy >= 0 && gy < N && gx >= 0 && gx < N) ? ib[gy * N + gx] : 0.f;
    }
    __syncthreads();
    for (int idx = tid; idx < 36 * 35; idx += 128) {
        int ly = idx / 35, lx = idx % 35;
        spair[ly * 36 + lx] = pk(simg[ly * 36 + lx], simg[ly * 36 + lx + 1]);
    }
    // (sync before compute provided by the per-phase post-load barrier)

    ull oacc[2][2];
    oacc[0][0] = 0ull; oacc[0][1] = 0ull; oacc[1][0] = 0ull; oacc[1][1] = 0ull;

    for (int i0 = 0; i0 < nc_in; i0 += CHG) {
        const int chg = (nc_in - i0 < CHG) ? (nc_in - i0) : CHG;
        __syncthreads();   // previous phase compute done

        // stage chg channels: x tiles, weights, biases
        for (int idx = tid; idx < chg * 1156; idx += 128) {
            int ci = idx / 1156, r = idx % 1156;
            int ly = r / 34, lx = r % 34;
            int gy = ty0 - 1 + ly, gx = tx0 - 1 + lx;
            const float* xb = xin + ((size_t)b * nc_in + (i0 + ci)) * N * N;
            sxs[ci * 1224 + ly * 36 + lx] =
                (gy >= 0 && gy < N && gx >= 0 && gx < N) ? xb[gy * N + gx] : 0.f;
        }
        for (int idx = tid; idx < chg * 300; idx += 128) {
            int ci = idx / 300, j = idx % 300;
            int g = o * nc_in + i0 + ci;
            sWd[ci * 300 + j] = tabDup[(size_t)slot * 19200 + (size_t)g * 300 + j];
        }
        if (tid < chg * 12) {
            int ci = tid / 12, j = tid % 12;
            int g = o * nc_in + i0 + ci;
            sBd[ci * 12 + j] = tabBDup[(size_t)slot * 768 + (size_t)g * 12 + j];
        }
        __syncthreads();

#pragma unroll 1
        for (int ci = 0; ci < chg; ci++) {
            const ull*   wd = sWd + ci * 300;
            const ull*   bd = sBd + ci * 12;
            const float* xc = sxs + ci * 1224;

#pragma unroll 1
            for (int kg = 0; kg < 3; kg++) {
                // x pairs for rows pqy+kg, pqy+kg+1
                ull xq[2][5];
#pragma unroll
                for (int rr = 0; rr < 2; rr++) {
                    const float* xr = xc + (pqy + kg + rr) * 36 + pqx;
                    float4 q4 = *reinterpret_cast<const float4*>(xr);
                    float2 q2 = *reinterpret_cast<const float2*>(xr + 4);
                    xq[rr][0] = pk(q4.x, q4.y); xq[rr][1] = pk(q4.y, q4.z);
                    xq[rr][2] = pk(q4.z, q4.w); xq[rr][3] = pk(q4.w, q2.x);
                    xq[rr][4] = pk(q2.x, q2.y);
                }

                ull acc[3][2][2];
#pragma unroll
                for (int j = 0; j < 3; j++) {
                    ull bb = bd[kg * 4 + j];
                    acc[j][0][0] = bb; acc[j][0][1] = bb;
                    acc[j][1][0] = bb; acc[j][1][1] = bb;
                }

                ull A[7], B[7];
                load_row(spair, pqy,     pqx, A);
                load_row(spair, pqy + 1, pqx, B);
                conv_step(wd, kg, 0, A, B, acc);
                load_row(spair, pqy + 2, pqx, A);
                conv_step(wd, kg, 1, B, A, acc);
                load_row(spair, pqy + 3, pqx, B);
                conv_step(wd, kg, 2, A, B, acc);
                load_row(spair, pqy + 4, pqx, A);
                conv_step(wd, kg, 3, B, A, acc);
                load_row(spair, pqy + 5, pqx, B);
                conv_step(wd, kg, 4, A, B, acc);

#pragma unroll
                for (int j = 0; j < 3; j++) {
                    oacc[0][0] = fma2(acc[j][0][0], xq[0][j],     oacc[0][0]);
                    oacc[0][1] = fma2(acc[j][0][1], xq[0][j + 2], oacc[0][1]);
                    oacc[1][0] = fma2(acc[j][1][0], xq[1][j],     oacc[1][0]);
                    oacc[1][1] = fma2(acc[j][1][1], xq[1][j + 2], oacc[1][1]);
                }
            }
        }
    }

    float* ob = out + ((size_t)b * NC + o) * N * N;
#pragma unroll
    for (int sy = 0; sy < 2; sy++) {
#pragma unroll
        for (int cp = 0; cp < 2; cp++) {
            float lo, hi;
            upk(oacc[sy][cp], lo, hi);
            int row = ty0 + pqy + sy, col = tx0 + pqx + 2 * cp;
            if (row > 0 && row < N - 1) {
                if (col > 0 && col < N - 1)         ob[row * N + col]     = elu_f(lo);
                if (col + 1 > 0 && col + 1 < N - 1) ob[row * N + col + 1] = elu_f(hi);
            }
        }
    }
}

// ---------------------------------------------------------------------------
__global__ void down_kernel(const float* __restrict__ in, float* __restrict__ out,
                            int C, int No)
{
    int idx = blockIdx.x * blockDim.x + threadIdx.x;
    int total = C * No * No;
    if (idx >= total) return;
    int c = idx / (No * No);
    int p = idx % (No * No);
    int h = p / No, w = p % No;
    int Ni = No * 2;
    const float* ib = in + (size_t)c * Ni * Ni;
    float sv = ib[(2 * h) * Ni + 2 * w] + ib[(2 * h) * Ni + 2 * w + 1]
             + ib[(2 * h + 1) * Ni + 2 * w] + ib[(2 * h + 1) * Ni + 2 * w + 1];
    out[idx] = 0.25f * sv;
}

__global__ void combine_kernel(const float* __restrict__ x0,
                               const float* __restrict__ x1,
                               const float* __restrict__ x2,
                               const float* __restrict__ w5, const float* __restrict__ b5,
                               const float* __restrict__ w6, const float* __restrict__ b6,
                               float* __restrict__ out)
{
    int idx = blockIdx.x * blockDim.x + threadIdx.x;
    if (idx >= 8 * 128 * 128) return;
    int b = idx / (128 * 128);
    int p = idx % (128 * 128);
    int h = p / 128, w = p % 128;
    float v[NC];
#pragma unroll
    for (int c = 0; c < NC; c++) {
        v[c] = x0[((size_t)b * NC + c) * 16384 + p]
             + x1[((size_t)b * NC + c) * 4096 + (h >> 1) * 64 + (w >> 1)]
             + x2[((size_t)b * NC + c) * 1024 + (h >> 2) * 32 + (w >> 2)];
    }
    float accv = b6[0];
#pragma unroll
    for (int o = 0; o < NC; o++) {
        float y = b5[o];
#pragma unroll
        for (int c = 0; c < NC; c++) y += w5[o * NC + c] * v[c];
        y = elu_f(y);
        accv += w6[o] * y;
    }
    out[idx] = accv;
}

// ---------------------------------------------------------------------------
extern "C" void kernel_launch(void* const* d_in, const int* in_sizes, int n_in,
                              void* d_out, int out_size)
{
    const float* image = (const float*)d_in[0];
    const float* x_in  = (const float*)d_in[1];
    const float* iW1   = (const float*)d_in[2];
    const float* ib1   = (const float*)d_in[3];
    const float* iW2   = (const float*)d_in[4];
    const float* ib2   = (const float*)d_in[5];
    const float* bW1   = (const float*)d_in[6];
    const float* bb1   = (const float*)d_in[7];
    const float* bW2   = (const float*)d_in[8];
    const float* bb2   = (const float*)d_in[9];
    const float* w5    = (const float*)d_in[10];
    const float* b5    = (const float*)d_in[11];
    const float* w6    = (const float*)d_in[12];
    const float* b6    = (const float*)d_in[13];

    float* base;
    cudaGetSymbolAddress((void**)&base, g_buf);
    float* img1 = base;                        // 32768
    float* img2 = img1 + 32768;                // 8192
    float* x0a  = img2 + 8192;                 // at 40960
    float* x0b  = x0a + 1048576;
    float* x1a  = x0b + 1048576;
    float* x1b  = x1a + 262144;
    float* x2a  = x1b + 262144;
    float* x2b  = x2a + 65536;
    float* tabW5 = x2b + 65536;                // 13*129600
    float* tabB  = tabW5 + 13 * 129600;        // 13*5184
    ull*   tabDup  = (ull*)(tabB + 13 * 5184); // 13*19200 ull
    ull*   tabBDup = tabDup + 13 * 19200;      // 13*768 ull

    cudaFuncSetAttribute(smmain_kernel,
                         cudaFuncAttributeMaxDynamicSharedMemorySize, 45120);

    // all tables upfront (x-independent)
    compose_kernel<<<(13 * 5184 + 127) / 128, 128>>>(
        iW1, ib1, iW2, ib2, bW1, bb1, bW2, bb2, tabW5, tabB, tabDup, tabBDup);

    // image pyramid
    down_kernel<<<(8 * 64 * 64 + 255) / 256, 256>>>(image, img1, 8, 64);
    down_kernel<<<(8 * 32 * 32 + 255) / 256, 256>>>(img1, img2, 8, 32);

    // init block (slot 0, nc_in=1, full-res only) with fused border
    smmain_kernel<<<dim3(20, 8, 8), 128, 45120>>>(image, img1, img2,
        x_in, x_in, x_in, x0a, x0a, x0a, tabDup, tabBDup, tabW5, tabB, 1, 0, 0);

    // downsample x
    down_kernel<<<(64 * 64 * 64 + 255) / 256, 256>>>(x0a, x1a, 64, 64);
    down_kernel<<<(64 * 32 * 32 + 255) / 256, 256>>>(x1a, x2a, 64, 32);

    float *xc = x0a, *xn = x0b;
    float *x1c = x1a, *x1n = x1b;
    float *x2c = x2a, *x2n = x2b;

    for (int t = 0; t < 4; t++) {
        smmain_kernel<<<dim3(28, 8, 8), 128, 45120>>>(image, img1, img2,
            xc, x1c, x2c, xn, x1n, x2n, tabDup, tabBDup, tabW5, tabB,
            8, 1 + 3 * t, 1);
        { float* tp = xc;  xc = xn;   xn = tp; }
        { float* tp = x1c; x1c = x1n; x1n = tp; }
        { float* tp = x2c; x2c = x2n; x2n = tp; }
    }

    combine_kernel<<<(8 * 128 * 128 + 255) / 256, 256>>>(
        xc, x1c, x2c, w5, b5, w6, b6, (float*)d_out);
}